// round 9
// baseline (speedup 1.0000x reference)
#include <cuda_runtime.h>

#define BATCH 2
#define SEQ 384
#define HID 128
#define TABLE (2 * SEQ + 1)   // 769
#define F4H (4 * HID)         // 512

// W pre-transposed: g_Wt[table][f][h] = W[h][table*128 + f]  (256 KB, L2/L1-resident)
__device__ float g_Wt[4][HID][HID];
// Folded per-table results: T[x][t][h] = pe_x[t] @ W_x^T  (+ bias folded into x=0)
__device__ float g_T[4][TABLE][HID];
// Fully fused table: T2[(d*8+sq)*8+sk][h] = relu(sum of 4 gathers + b). 25.2 MB.
__device__ float g_T2[TABLE * 64 * HID];

// ---------------------------------------------------------------------------
// Stage 0: transpose W [128h][512f] -> g_Wt[4][128f][128h].
// Standard 32x32 smem-tile transpose; both gmem sides fully coalesced.
// ---------------------------------------------------------------------------
__global__ __launch_bounds__(256) void transpose_kernel(const float* __restrict__ W) {
    __shared__ float tile[32][33];
    const int f0 = blockIdx.x * 32;     // 0..480
    const int h0 = blockIdx.y * 32;     // 0..96
    const int tx = threadIdx.x;         // 0..31
    const int ty = threadIdx.y;         // 0..7

#pragma unroll
    for (int i = 0; i < 4; i++)
        tile[ty + 8 * i][tx] = W[(h0 + ty + 8 * i) * F4H + f0 + tx];
    __syncthreads();

    const int table = f0 >> 7;          // tiles never straddle a 128 boundary
#pragma unroll
    for (int i = 0; i < 4; i++) {
        int fp = (f0 & 127) + ty + 8 * i;
        g_Wt[table][fp][h0 + tx] = tile[tx][ty + 8 * i];
    }
}

// ---------------------------------------------------------------------------
// Stage 1: T[x] = pe_x @ W_x^T.  Grid (97, 4), block 256.
// No W staging: each warp reads one contiguous 128B line of g_Wt per f
// (L1-hit broadcast; whole 64KB slice is L1-resident across the 8 t-rows).
// pe in smem padded to 129 -> conflict-free broadcast reads.
// ---------------------------------------------------------------------------
__global__ __launch_bounds__(256) void table_gemm_kernel(
    const float* __restrict__ pe0, const float* __restrict__ pe1,
    const float* __restrict__ pe2, const float* __restrict__ pe3,
    const float* __restrict__ bias) {
    const int table = blockIdx.y;
    const int tbase = blockIdx.x * 8;
    const float* pe = (table == 0) ? pe0 : (table == 1) ? pe1 : (table == 2) ? pe2 : pe3;

    __shared__ float pe_s[8][129];      // pad -> bank = t + f, conflict-free

    for (int idx = threadIdx.x; idx < 8 * HID; idx += 256) {
        int t = idx >> 7, f = idx & 127;
        int gt = tbase + t;
        pe_s[t][f] = (gt < TABLE) ? pe[gt * HID + f] : 0.0f;
    }
    __syncthreads();

    const int w_id = threadIdx.x >> 5;
    const int lane = threadIdx.x & 31;
    const int tg = w_id >> 2;            // 0..1
    const int hq = w_id & 3;             // 0..3  (warp-uniform)
    const int hg = lane >> 2;            // 0..7
    const int lt = lane & 3;             // 0..3
    const int t = tg * 4 + lt;           // 0..7
    const int h0 = (hq * 8 + hg) * 4;    // warp spans 128B contiguous per f

    const float* __restrict__ wt = &g_Wt[table][0][0];

    float a0 = 0.f, a1 = 0.f, a2 = 0.f, a3 = 0.f;
#pragma unroll 8
    for (int f = 0; f < HID; f++) {
        float a = pe_s[t][f];
        float4 w = __ldg((const float4*)&wt[f * HID + h0]);
        a0 += a * w.x; a1 += a * w.y; a2 += a * w.z; a3 += a * w.w;
    }

    const int gt = tbase + t;
    if (gt < TABLE) {
        if (table == 0) {
            float4 bb = *(const float4*)&bias[h0];
            a0 += bb.x; a1 += bb.y; a2 += bb.z; a3 += bb.w;
        }
        *(float4*)&g_T[table][gt][h0] = make_float4(a0, a1, a2, a3);
    }
}

// ---------------------------------------------------------------------------
// Stage 1b: fully fused table.
// T2[d][sq][sk][:] = relu(T0[d] + T1[d-sk] + T2[d+sq] + T3[d+sq-sk])
// (bias already folded into T0; clamped entries never read by real data)
// ---------------------------------------------------------------------------
__global__ __launch_bounds__(256) void build_kernel() {
    const int warp = (blockIdx.x << 3) + (threadIdx.x >> 5);
    const int lane = threadIdx.x & 31;

    const int d  = warp >> 6;
    const int sq = (warp >> 3) & 7;
    const int sk = warp & 7;

    const int ise = max(d - sk, 0);
    const int ies = min(d + sq, TABLE - 1);
    const int iee = min(max(d + sq - sk, 0), TABLE - 1);

    const float4* T0 = (const float4*)g_T[0];
    const float4* T1 = (const float4*)g_T[1];
    const float4* T2 = (const float4*)g_T[2];
    const float4* T3 = (const float4*)g_T[3];

    float4 v0 = __ldg(T0 + d   * 32 + lane);
    float4 v1 = __ldg(T1 + ise * 32 + lane);
    float4 v2 = __ldg(T2 + ies * 32 + lane);
    float4 v3 = __ldg(T3 + iee * 32 + lane);

    float4 r;
    r.x = fmaxf(v0.x + v1.x + v2.x + v3.x, 0.0f);
    r.y = fmaxf(v0.y + v1.y + v2.y + v3.y, 0.0f);
    r.z = fmaxf(v0.z + v1.z + v2.z + v3.z, 0.0f);
    r.w = fmaxf(v0.w + v1.w + v2.w + v3.w, 0.0f);

    ((float4*)g_T2)[warp * 32 + lane] = r;
}

// ---------------------------------------------------------------------------
// Stage 2: out[b,q,k,:] = T2row[(d,sq,sk)]. One L2-resident gather + one
// streaming (evict-first) store per 512B row.
// ---------------------------------------------------------------------------
__global__ __launch_bounds__(256) void fuse_kernel(
    const int* __restrict__ pos_s, const int* __restrict__ pos_e,
    float* __restrict__ out) {
    const int warp = (blockIdx.x << 3) + (threadIdx.x >> 5);
    const int lane = threadIdx.x & 31;

    const int k = warp % SEQ;
    const int bq = warp / SEQ;            // b*SEQ + q
    const int bbase = (bq / SEQ) * SEQ;   // b*SEQ

    const int aq = __ldg(pos_s + bq);
    const int eq = __ldg(pos_e + bq);
    const int ck = __ldg(pos_s + bbase + k);
    const int dk = __ldg(pos_e + bbase + k);

    const int d  = aq - ck + SEQ;
    const int sq = eq - aq;               // in [0,7]
    const int sk = dk - ck;               // in [0,7]
    const int row = (d << 6) + (sq << 3) + sk;

    float4 v = __ldg((const float4*)g_T2 + row * 32 + lane);
    __stcs((float4*)out + warp * 32 + lane, v);
}

extern "C" void kernel_launch(void* const* d_in, const int* in_sizes, int n_in,
                              void* d_out, int out_size) {
    const int* pos_s   = (const int*)d_in[0];
    const int* pos_e   = (const int*)d_in[1];
    const float* pe_ss = (const float*)d_in[2];
    const float* pe_se = (const float*)d_in[3];
    const float* pe_es = (const float*)d_in[4];
    const float* pe_ee = (const float*)d_in[5];
    const float* W     = (const float*)d_in[6];
    const float* bias  = (const float*)d_in[7];
    float* out = (float*)d_out;

    transpose_kernel<<<dim3(16, 4), dim3(32, 8)>>>(W);

    dim3 g1((TABLE + 7) / 8, 4);                   // 97 x 4 = 388 blocks
    table_gemm_kernel<<<g1, 256>>>(pe_ss, pe_se, pe_es, pe_ee, bias);

    build_kernel<<<(TABLE * 64) / 8, 256>>>();     // 6152 blocks

    const int rows = BATCH * SEQ * SEQ;            // 294912
    fuse_kernel<<<rows / 8, 256>>>(pos_s, pos_e, out);
}